// round 9
// baseline (speedup 1.0000x reference)
#include <cuda_runtime.h>
#include <math.h>
#include <stdint.h>

#define NN    30000
#define LSEQ  5
#define KFAN  16
#define DIN   128
#define NG    512   // 2 dirs * 4 gates * 64 hidden
#define NB    8     // nodes per recurrence block

// ---------------- scratch (device globals: sanctioned allocation path) ----
__device__ float g_xg[NN * LSEQ * NG];   // content input-gate activations
__device__ float g_P0[NN * NG];          // P_a = c_a @ Wih_na^T + b
__device__ float g_P1[NN * NG];          // P_b = c_b @ Wih_nb^T + b
__device__ float g_c0[NN * 128];         // c_a
__device__ float g_c1[NN * 128];         // c_b
__device__ float g_n0[NN * 128];         // n_aa
__device__ float g_n1[NN * 128];         // n_ba
__device__ float g_n2[NN * 128];         // n_ab
__device__ float g_n3[NN * 128];         // n_bb

// ---------------- fast transcendentals (MUFU.TANH) -------------------------
__device__ __forceinline__ float ftanh(float x) {
    float y;
    asm("tanh.approx.f32 %0, %1;" : "=f"(y) : "f"(x));
    return y;
}
__device__ __forceinline__ float fsigmoid(float x) {
    return fmaf(ftanh(0.5f * x), 0.5f, 0.5f);
}
__device__ __forceinline__ uint32_t f2tf32(float x) {
    uint32_t u;
    asm("cvt.rna.tf32.f32 %0, %1;" : "=r"(u) : "f"(x));
    return u;
}

// ---------------- GEMM (tf32 tensor cores, K-chunked) ----------------------
// C[m, j] = bias[j] + sum_d A[m,d] * W[j,d]
// A: [M,128] f32 row-major.  W: [512,128] f32 row-major.
// Block tile 128(M) x 128(N); K processed in 2 chunks of 64 staged in smem
// as tf32 (69KB total) -> 2 blocks/SM co-resident, so one block's staging
// (LDG + cvt + STS) overlaps the other's MMA phase.
// 256 threads, 8 warps in 4(M) x 2(N); warp = 32x64 via 2x8 m16n8k8 atoms.
// blockIdx.x = N slice (fastest -> 4 N-blocks share an A slab via L2).
#define KC    64                 // k per chunk
#define KST   68                 // smem stride (68 % 32 == 4: conflict-free)
__global__ __launch_bounds__(256, 2) void gemm_gates(
    const float* __restrict__ A, int M,
    const float* __restrict__ W,
    const float* __restrict__ bias,
    float* __restrict__ C)
{
    extern __shared__ float sm[];
    uint32_t* Au = reinterpret_cast<uint32_t*>(sm);             // [128 m][KST]
    uint32_t* Bu = reinterpret_cast<uint32_t*>(sm) + 128 * KST; // [128 n][KST]
    __shared__ float sBias[128];
    const int tid = threadIdx.x;
    const int j0 = blockIdx.x * 128;   // N slice (0..3)
    const int m0 = blockIdx.y * 128;

    if (tid < 128) sBias[tid] = bias[j0 + tid];

    const int lane = tid & 31;
    const int warp = tid >> 5;     // 0..7
    const int wm = warp & 3;       // 4 m-slices of 32
    const int wn = warp >> 2;      // 2 n-slices of 64
    const int g  = lane >> 2;      // group id (0..7)
    const int tg = lane & 3;       // thread in group (0..3)

    float acc[2][8][4];
    #pragma unroll
    for (int ma = 0; ma < 2; ++ma)
        #pragma unroll
        for (int na = 0; na < 8; ++na)
            #pragma unroll
            for (int e = 0; e < 4; ++e) acc[ma][na][e] = 0.f;

    #pragma unroll
    for (int kc = 0; kc < 2; ++kc) {
        if (kc > 0) __syncthreads();   // protect smem reuse across chunks

        // stage A chunk -> tf32 smem [m][k], 128 rows x 16 f4
        #pragma unroll
        for (int p = 0; p < 8; ++p) {
            int idx = tid + p * 256;   // 0..2047
            int row = idx >> 4;        // 0..127
            int c4  = idx & 15;        // f4 along chunk k
            int gm = m0 + row;
            float4 v = make_float4(0.f, 0.f, 0.f, 0.f);
            if (gm < M)
                v = reinterpret_cast<const float4*>(A)[(size_t)gm * 32 + kc * 16 + c4];
            uint4 u = make_uint4(f2tf32(v.x), f2tf32(v.y), f2tf32(v.z), f2tf32(v.w));
            *reinterpret_cast<uint4*>(&Au[row * KST + c4 * 4]) = u;
        }
        // stage W chunk -> tf32 smem [n][k]
        #pragma unroll
        for (int p = 0; p < 8; ++p) {
            int idx = tid + p * 256;
            int row = idx >> 4;        // n within slice
            int c4  = idx & 15;
            float4 v = reinterpret_cast<const float4*>(W)[(size_t)(j0 + row) * 32 + kc * 16 + c4];
            uint4 u = make_uint4(f2tf32(v.x), f2tf32(v.y), f2tf32(v.z), f2tf32(v.w));
            *reinterpret_cast<uint4*>(&Bu[row * KST + c4 * 4]) = u;
        }
        __syncthreads();

        #pragma unroll
        for (int ks = 0; ks < 8; ++ks) {
            const int k0 = ks * 8;
            uint32_t af[2][4];
            #pragma unroll
            for (int ma = 0; ma < 2; ++ma) {
                const uint32_t* ap = Au + (wm * 32 + ma * 16 + g) * KST + k0 + tg;
                af[ma][0] = ap[0];
                af[ma][2] = ap[4];
                af[ma][1] = ap[8 * KST];
                af[ma][3] = ap[8 * KST + 4];
            }
            uint32_t bf[8][2];
            #pragma unroll
            for (int na = 0; na < 8; ++na) {
                const uint32_t* bp = Bu + (wn * 64 + na * 8 + g) * KST + k0 + tg;
                bf[na][0] = bp[0];
                bf[na][1] = bp[4];
            }
            #pragma unroll
            for (int ma = 0; ma < 2; ++ma)
                #pragma unroll
                for (int na = 0; na < 8; ++na)
                    asm volatile(
                        "mma.sync.aligned.m16n8k8.row.col.f32.tf32.tf32.f32 "
                        "{%0,%1,%2,%3}, {%4,%5,%6,%7}, {%8,%9}, {%0,%1,%2,%3};"
                        : "+f"(acc[ma][na][0]), "+f"(acc[ma][na][1]),
                          "+f"(acc[ma][na][2]), "+f"(acc[ma][na][3])
                        : "r"(af[ma][0]), "r"(af[ma][1]), "r"(af[ma][2]), "r"(af[ma][3]),
                          "r"(bf[na][0]), "r"(bf[na][1]));
        }
    }

    // epilogue: bias + store (c0,c1 contiguous pair; c2,c3 at row+8)
    #pragma unroll
    for (int ma = 0; ma < 2; ++ma) {
        #pragma unroll
        for (int half = 0; half < 2; ++half) {
            int gm = m0 + wm * 32 + ma * 16 + g + half * 8;
            if (gm < M) {
                float* Crow = C + (size_t)gm * NG + j0;
                #pragma unroll
                for (int na = 0; na < 8; ++na) {
                    int n = wn * 64 + na * 8 + tg * 2;
                    float2 o;
                    o.x = acc[ma][na][half * 2 + 0] + sBias[n];
                    o.y = acc[ma][na][half * 2 + 1] + sBias[n + 1];
                    *reinterpret_cast<float2*>(Crow + n) = o;
                }
            }
        }
    }
}

// ---------------- bi-LSTM recurrence + mean -------------------------------
// v2 (measured-good): idx table in smem, double-buffered xg gathers, dual
// accumulators, MUFU.TANH fast gates. Thread tid = gate id j (dir = j>>8).
__global__ __launch_bounds__(512, 1) void recur_kernel(
    const float* __restrict__ xg,
    const int* __restrict__ idx,
    int T,
    const float* __restrict__ Whh,   // [512 * 64] row-major
    float* __restrict__ out)         // [NN * 128]  ([fwd 64 | bwd 64])
{
    __shared__ float h_s[NB][128];
    __shared__ float g_s[NB][NG];
    __shared__ int   sIdx[NB * 17];   // idx rows, padded stride 17 (T<=16)
    const int tid = threadIdx.x;
    const int dir = tid >> 8;
    const int node0 = blockIdx.x * NB;

    if (tid < NB * T) {
        int i = tid / T, t = tid % T;
        int seq = (node0 + i) * T + t;
        sIdx[i * 17 + t] = idx ? idx[seq] : seq;
    }

    float whh[64];
    {
        const float4* wp = reinterpret_cast<const float4*>(Whh + (size_t)tid * 64);
        #pragma unroll
        for (int e4 = 0; e4 < 16; ++e4) {
            float4 v = wp[e4];
            whh[e4 * 4 + 0] = v.x; whh[e4 * 4 + 1] = v.y;
            whh[e4 * 4 + 2] = v.z; whh[e4 * 4 + 3] = v.w;
        }
    }

    float cst[2]  = {0.f, 0.f};
    float hsum[2] = {0.f, 0.f};
    #pragma unroll
    for (int q = 0; q < 2; ++q) {
        int u = tid + q * 512;
        h_s[u >> 7][u & 127] = 0.f;
    }
    __syncthreads();

    float cur[NB], nxt[NB];
    #pragma unroll
    for (int i = 0; i < NB; ++i) nxt[i] = 0.f;
    {
        const int trow = dir ? (T - 1) : 0;
        #pragma unroll
        for (int i = 0; i < NB; ++i)
            cur[i] = xg[(size_t)sIdx[i * 17 + trow] * NG + tid];
    }

    for (int t = 0; t < T; ++t) {
        if (t + 1 < T) {
            const int trow = dir ? (T - 2 - t) : (t + 1);
            #pragma unroll
            for (int i = 0; i < NB; ++i)
                nxt[i] = xg[(size_t)sIdx[i * 17 + trow] * NG + tid];
        }

        #pragma unroll
        for (int i = 0; i < NB; ++i) {
            const float4* h4 = reinterpret_cast<const float4*>(&h_s[i][dir * 64]);
            float a0 = cur[i], a1 = 0.f;
            #pragma unroll
            for (int e4 = 0; e4 < 16; e4 += 2) {
                float4 ha = h4[e4];
                float4 hb = h4[e4 + 1];
                a0 += whh[e4 * 4 + 0] * ha.x;
                a0 += whh[e4 * 4 + 1] * ha.y;
                a0 += whh[e4 * 4 + 2] * ha.z;
                a0 += whh[e4 * 4 + 3] * ha.w;
                a1 += whh[e4 * 4 + 4] * hb.x;
                a1 += whh[e4 * 4 + 5] * hb.y;
                a1 += whh[e4 * 4 + 6] * hb.z;
                a1 += whh[e4 * 4 + 7] * hb.w;
            }
            g_s[i][tid] = a0 + a1;
        }
        __syncthreads();

        #pragma unroll
        for (int q = 0; q < 2; ++q) {
            int u = tid + q * 512;
            int i = u >> 7, r = u & 127;
            int dd = r >> 6, e = r & 63;
            const float* gg = &g_s[i][dd * 256];
            float si = fsigmoid(gg[e]);
            float sf = fsigmoid(gg[64 + e]);
            float so = fsigmoid(gg[192 + e]);
            float gt = ftanh(gg[128 + e]);
            float c = sf * cst[q] + si * gt;
            float h = so * ftanh(c);
            cst[q] = c;
            h_s[i][r] = h;
            hsum[q] += h;
        }
        __syncthreads();

        #pragma unroll
        for (int i = 0; i < NB; ++i) cur[i] = nxt[i];
    }

    const float invT = 1.f / (float)T;
    #pragma unroll
    for (int q = 0; q < 2; ++q) {
        int u = tid + q * 512;
        int i = u >> 7, r = u & 127;
        out[(size_t)(node0 + i) * 128 + r] = hsum[q] * invT;
    }
}

// ---------------- attention combine ---------------------------------------
__global__ void combine_kernel(
    const float* __restrict__ cA, const float* __restrict__ cB,
    const float* __restrict__ nAA, const float* __restrict__ nBA,
    const float* __restrict__ nAB, const float* __restrict__ nBB,
    const float* __restrict__ attnA, const float* __restrict__ attnB,
    float* __restrict__ out)
{
    int gw   = (blockIdx.x * blockDim.x + threadIdx.x) >> 5;
    int lane = threadIdx.x & 31;
    if (gw >= 2 * NN) return;
    int tp = gw >= NN;
    int node = gw - tp * NN;

    const float* c  = (tp ? cB  : cA)  + (size_t)node * 128;
    const float* n1 = (tp ? nAB : nAA) + (size_t)node * 128;
    const float* n2 = (tp ? nBB : nBA) + (size_t)node * 128;
    const float* at = tp ? attnB : attnA;

    float4 c4  = reinterpret_cast<const float4*>(c)[lane];
    float4 n14 = reinterpret_cast<const float4*>(n1)[lane];
    float4 n24 = reinterpret_cast<const float4*>(n2)[lane];
    float4 a1  = reinterpret_cast<const float4*>(at)[lane];
    float4 a2  = reinterpret_cast<const float4*>(at + 128)[lane];

    float d0 = a1.x * c4.x + a1.y * c4.y + a1.z * c4.z + a1.w * c4.w;
    float dc = a2.x * c4.x + a2.y * c4.y + a2.z * c4.z + a2.w * c4.w;
    float d1 = a2.x * n14.x + a2.y * n14.y + a2.z * n14.z + a2.w * n14.w;
    float d2 = a2.x * n24.x + a2.y * n24.y + a2.z * n24.z + a2.w * n24.w;
    #pragma unroll
    for (int o = 16; o > 0; o >>= 1) {
        d0 += __shfl_xor_sync(0xffffffffu, d0, o);
        dc += __shfl_xor_sync(0xffffffffu, dc, o);
        d1 += __shfl_xor_sync(0xffffffffu, d1, o);
        d2 += __shfl_xor_sync(0xffffffffu, d2, o);
    }
    float s0 = d0 + dc; s0 = s0 > 0.f ? s0 : 0.01f * s0;
    float s1 = d0 + d1; s1 = s1 > 0.f ? s1 : 0.01f * s1;
    float s2 = d0 + d2; s2 = s2 > 0.f ? s2 : 0.01f * s2;
    float mx = fmaxf(s0, fmaxf(s1, s2));
    float e0 = expf(s0 - mx), e1 = expf(s1 - mx), e2 = expf(s2 - mx);
    float inv = 1.f / (e0 + e1 + e2);
    e0 *= inv; e1 *= inv; e2 *= inv;

    float4 o4;
    o4.x = e0 * c4.x + e1 * n14.x + e2 * n24.x;
    o4.y = e0 * c4.y + e1 * n14.y + e2 * n24.y;
    o4.z = e0 * c4.z + e1 * n14.z + e2 * n24.z;
    o4.w = e0 * c4.w + e1 * n14.w + e2 * n24.w;
    reinterpret_cast<float4*>(out + (size_t)tp * NN * 128 + (size_t)node * 128)[lane] = o4;
}

// ---------------- launch ---------------------------------------------------
extern "C" void kernel_launch(void* const* d_in, const int* in_sizes, int n_in,
                              void* d_out, int out_size)
{
    const float* feats_a = (const float*)d_in[0];
    const float* feats_b = (const float*)d_in[1];
    const float* Wih_ca = (const float*)d_in[2];
    const float* Whh_ca = (const float*)d_in[3];
    const float* b_ca   = (const float*)d_in[4];
    const float* Wih_cb = (const float*)d_in[5];
    const float* Whh_cb = (const float*)d_in[6];
    const float* b_cb   = (const float*)d_in[7];
    const float* Wih_na = (const float*)d_in[8];
    const float* Whh_na = (const float*)d_in[9];
    const float* b_na   = (const float*)d_in[10];
    const float* Wih_nb = (const float*)d_in[11];
    const float* Whh_nb = (const float*)d_in[12];
    const float* b_nb   = (const float*)d_in[13];
    const float* attn_a = (const float*)d_in[14];
    const float* attn_b = (const float*)d_in[15];
    const int* idx_a_a = (const int*)d_in[16];
    const int* idx_b_a = (const int*)d_in[17];
    const int* idx_a_b = (const int*)d_in[18];
    const int* idx_b_b = (const int*)d_in[19];
    float* out = (float*)d_out;
    (void)in_sizes; (void)n_in; (void)out_size;

    float *xg, *P0, *P1, *c0, *c1, *n0, *n1, *n2, *n3;
    cudaGetSymbolAddress((void**)&xg, g_xg);
    cudaGetSymbolAddress((void**)&P0, g_P0);
    cudaGetSymbolAddress((void**)&P1, g_P1);
    cudaGetSymbolAddress((void**)&c0, g_c0);
    cudaGetSymbolAddress((void**)&c1, g_c1);
    cudaGetSymbolAddress((void**)&n0, g_n0);
    cudaGetSymbolAddress((void**)&n1, g_n1);
    cudaGetSymbolAddress((void**)&n2, g_n2);
    cudaGetSymbolAddress((void**)&n3, g_n3);

    const size_t GSM = 2u * 128u * KST * sizeof(float);  // 69632B -> 2 blocks/SM
    cudaFuncSetAttribute(gemm_gates, cudaFuncAttributeMaxDynamicSharedMemorySize, (int)GSM);

    dim3 ggC(4, (NN * LSEQ + 127) / 128);   // N-slices fastest: A slab read once
    dim3 ggP(4, (NN + 127) / 128);
    const int RB = NN / NB;  // 3750

    // content bi-LSTMs
    gemm_gates<<<ggC, 256, GSM>>>(feats_a, NN * LSEQ, Wih_ca, b_ca, xg);
    recur_kernel<<<RB, 512>>>(xg, nullptr, LSEQ, Whh_ca, c0);
    gemm_gates<<<ggC, 256, GSM>>>(feats_b, NN * LSEQ, Wih_cb, b_cb, xg);
    recur_kernel<<<RB, 512>>>(xg, nullptr, LSEQ, Whh_cb, c1);

    // per-src-node neighbor input gates (amortizes the gather GEMM 16x)
    gemm_gates<<<ggP, 256, GSM>>>(c0, NN, Wih_na, b_na, P0);
    gemm_gates<<<ggP, 256, GSM>>>(c1, NN, Wih_nb, b_nb, P1);

    // neighbor bi-LSTMs; P0 consumers adjacent, then P1 (L2 reuse of 61MB P)
    recur_kernel<<<RB, 512>>>(P0, idx_a_a, KFAN, Whh_na, n0);
    recur_kernel<<<RB, 512>>>(P0, idx_a_b, KFAN, Whh_na, n2);
    recur_kernel<<<RB, 512>>>(P1, idx_b_a, KFAN, Whh_nb, n1);
    recur_kernel<<<RB, 512>>>(P1, idx_b_b, KFAN, Whh_nb, n3);

    // attention combine
    combine_kernel<<<(2 * NN * 32 + 255) / 256, 256>>>(
        c0, c1, n0, n1, n2, n3, attn_a, attn_b, out);
}